// round 6
// baseline (speedup 1.0000x reference)
#include <cuda_runtime.h>
#include <cuda_bf16.h>
#include <cuda_fp16.h>
#include <cstdint>

#define NUM_USERS 30000
#define NUM_ITEMS 70000
#define NTOT      100000
#define D         128
#define NNZ       1000000
#define NLAYERS   3
#define BATCH     16384
#define FD        512   // D * (1 + NLAYERS)

#define SCAN_BS   1024
#define SCAN_NB   ((NTOT + SCAN_BS - 1) / SCAN_BS)  // 98

// Scratch (no cudaMalloc allowed)
__device__ float  g_final[(size_t)NTOT * FD];
__device__ float  g_Lx[(size_t)NTOT * D];
__device__ __half g_fh16[(size_t)NTOT * D];   // fp16 copy of current-layer features (gather plane)
__device__ int    g_cnt[NTOT];
__device__ int    g_start[NTOT + 1];
__device__ int    g_cursor[NTOT];
__device__ int    g_ecol[NNZ];
__device__ float  g_eval[NNZ];
__device__ int    g_bsum[SCAN_NB];
__device__ int    g_boff[SCAN_NB];
// Pre-split, pre-transposed weight images: per (layer, phase{lin,int}, split{hi,mid})
__device__ uint32_t g_wimg[3 * 2 * 2 * 8192];

// ======================= mma.sync helpers =======================
__device__ __forceinline__ uint32_t smem_u32(const void* p) {
    uint32_t a;
    asm("{ .reg .u64 t; cvta.to.shared.u64 t, %1; cvt.u32.u64 %0, t; }" : "=r"(a) : "l"(p));
    return a;
}
__device__ __forceinline__ void ldsm4(uint32_t* r, uint32_t addr) {
    asm volatile("ldmatrix.sync.aligned.m8n8.x4.shared.b16 {%0,%1,%2,%3}, [%4];"
                 : "=r"(r[0]), "=r"(r[1]), "=r"(r[2]), "=r"(r[3]) : "r"(addr));
}
__device__ __forceinline__ void mma16816(float* d, const uint32_t* a, uint32_t b0, uint32_t b1) {
    asm volatile(
        "mma.sync.aligned.m16n8k16.row.col.f32.bf16.bf16.f32 "
        "{%0,%1,%2,%3}, {%4,%5,%6,%7}, {%8,%9}, {%0,%1,%2,%3};"
        : "+f"(d[0]), "+f"(d[1]), "+f"(d[2]), "+f"(d[3])
        : "r"(a[0]), "r"(a[1]), "r"(a[2]), "r"(a[3]), "r"(b0), "r"(b1));
}
__device__ __forceinline__ uint32_t pack2(__nv_bfloat16 lo, __nv_bfloat16 hi) {
    return ((uint32_t)__bfloat16_as_ushort(hi) << 16) | (uint32_t)__bfloat16_as_ushort(lo);
}

#define TPITCH_B 272
#define TILE_B   (128 * TPITCH_B)

// ---------------------------------------------------------------------------
// Init: fp32 slice 0 + fp16 gather plane
// ---------------------------------------------------------------------------
__global__ void k_init(const float* __restrict__ uE, const float* __restrict__ iE) {
    int idx = blockIdx.x * blockDim.x + threadIdx.x;
    const int total = NTOT * (D / 4);
    if (idx >= total) return;
    int r = idx >> 5;
    int q = idx & 31;
    float4 v = (r < NUM_USERS)
        ? ((const float4*)uE)[(size_t)r * (D / 4) + q]
        : ((const float4*)iE)[(size_t)(r - NUM_USERS) * (D / 4) + q];
    ((float4*)g_final)[(size_t)r * (FD / 4) + q] = v;
    __half2 h0 = __floats2half2_rn(v.x, v.y);
    __half2 h1 = __floats2half2_rn(v.z, v.w);
    uint2 packed = make_uint2(*(uint32_t*)&h0, *(uint32_t*)&h1);
    ((uint2*)g_fh16)[(size_t)r * (D / 4) + q] = packed;
}

// ---------------------------------------------------------------------------
// Weight split/transpose precompute (once). B[n][k] = W[k][n], hi/mid bf16.
// ---------------------------------------------------------------------------
__global__ void k_wsplit(const float* __restrict__ Wlin, const float* __restrict__ Wint) {
    int idx = blockIdx.x * blockDim.x + threadIdx.x;
    const int total = 3 * 2 * 128 * 64;
    if (idx >= total) return;
    int k2 = idx & 63;
    int n  = (idx >> 6) & 127;
    int lp = idx >> 13;
    int p  = lp & 1;
    int l  = lp >> 1;
    int k  = k2 * 2;
    const float* W = (p ? Wint : Wlin) + (size_t)l * D * D;
    float w0 = W[(size_t)k * 128 + n];
    float w1 = W[(size_t)(k + 1) * 128 + n];
    __nv_bfloat16 h0 = __float2bfloat16(w0);
    __nv_bfloat16 h1 = __float2bfloat16(w1);
    __nv_bfloat16 m0 = __float2bfloat16(w0 - __bfloat162float(h0));
    __nv_bfloat16 m1 = __float2bfloat16(w1 - __bfloat162float(h1));
    int baseH = ((l * 2 + p) * 2 + 0) * 8192;
    int baseM = ((l * 2 + p) * 2 + 1) * 8192;
    g_wimg[baseH + n * 64 + k2] = pack2(h0, h1);
    g_wimg[baseM + n * 64 + k2] = pack2(m0, m1);
}

// ---------------------------------------------------------------------------
// CSR build
// ---------------------------------------------------------------------------
__global__ void k_zero_cnt() {
    int i = blockIdx.x * blockDim.x + threadIdx.x;
    if (i < NTOT) g_cnt[i] = 0;
}
__global__ void k_count(const int* __restrict__ rows) {
    int e = blockIdx.x * blockDim.x + threadIdx.x;
    if (e < NNZ) atomicAdd(&g_cnt[rows[e]], 1);
}
__global__ void k_scan1() {
    __shared__ int wsum[8];
    int t = threadIdx.x;
    int base = blockIdx.x * SCAN_BS + t * 4;
    int c0 = 0, c1 = 0, c2 = 0, c3 = 0;
    if (base + 3 < NTOT) {
        int4 c = *(const int4*)(g_cnt + base);
        c0 = c.x; c1 = c.y; c2 = c.z; c3 = c.w;
    } else {
        if (base + 0 < NTOT) c0 = g_cnt[base + 0];
        if (base + 1 < NTOT) c1 = g_cnt[base + 1];
        if (base + 2 < NTOT) c2 = g_cnt[base + 2];
        if (base + 3 < NTOT) c3 = g_cnt[base + 3];
    }
    int tot = c0 + c1 + c2 + c3;
    int inc = tot;
    #pragma unroll
    for (int d = 1; d < 32; d <<= 1) {
        int v = __shfl_up_sync(0xffffffffu, inc, d);
        if ((t & 31) >= d) inc += v;
    }
    if ((t & 31) == 31) wsum[t >> 5] = inc;
    __syncthreads();
    if (t < 8) {
        int v = wsum[t];
        int wi = v;
        #pragma unroll
        for (int d = 1; d < 8; d <<= 1) {
            int u = __shfl_up_sync(0xffu, wi, d);
            if (t >= d) wi += u;
        }
        wsum[t] = wi - v;
        if (t == 7) g_bsum[blockIdx.x] = wi;
    }
    __syncthreads();
    int off = wsum[t >> 5] + (inc - tot);
    if (base + 0 < NTOT) g_start[base + 0] = off;
    if (base + 1 < NTOT) g_start[base + 1] = off + c0;
    if (base + 2 < NTOT) g_start[base + 2] = off + c0 + c1;
    if (base + 3 < NTOT) g_start[base + 3] = off + c0 + c1 + c2;
}
__global__ void k_scan2() {
    __shared__ int wsum[4];
    int t = threadIdx.x;
    int v = (t < SCAN_NB) ? g_bsum[t] : 0;
    int inc = v;
    #pragma unroll
    for (int d = 1; d < 32; d <<= 1) {
        int u = __shfl_up_sync(0xffffffffu, inc, d);
        if ((t & 31) >= d) inc += u;
    }
    if ((t & 31) == 31) wsum[t >> 5] = inc;
    __syncthreads();
    if (t < 4) {
        int w = wsum[t];
        int wi = w;
        #pragma unroll
        for (int d = 1; d < 4; d <<= 1) {
            int u = __shfl_up_sync(0xfu, wi, d);
            if (t >= d) wi += u;
        }
        wsum[t] = wi - w;
    }
    __syncthreads();
    if (t < SCAN_NB) g_boff[t] = wsum[t >> 5] + (inc - v);
    if (t == 0) g_start[NTOT] = NNZ;
}
__global__ void k_scan3() {
    int i = blockIdx.x * blockDim.x + threadIdx.x;
    if (i >= NTOT) return;
    int s = g_start[i] + g_boff[i / SCAN_BS];
    g_start[i] = s;
    g_cursor[i] = s;
}
__global__ void k_scatter(const int* __restrict__ rows, const int* __restrict__ cols,
                          const float* __restrict__ vals) {
    int e = blockIdx.x * blockDim.x + threadIdx.x;
    if (e >= NNZ) return;
    int p = atomicAdd(&g_cursor[rows[e]], 1);
    g_ecol[p] = cols[e];
    g_eval[p] = vals[e];
}

// ---------------------------------------------------------------------------
// SpMM gather from fp16 plane: warp per row, 8-edge unroll (MLP 8), 8B/lane.
// ---------------------------------------------------------------------------
__global__ void k_spmm_h() {
    int r = blockIdx.x * (blockDim.x >> 5) + (threadIdx.x >> 5);
    if (r >= NTOT) return;
    int lane = threadIdx.x & 31;
    int s = g_start[r];
    int e = g_start[r + 1];
    float4 acc = make_float4(0.f, 0.f, 0.f, 0.f);
    for (int base = s; base < e; base += 32) {
        int idx = base + lane;
        int c = 0; float v = 0.f;
        if (idx < e) { c = g_ecol[idx]; v = g_eval[idx]; }
        int cnt = min(32, e - base);
        int j = 0;
        for (; j + 8 <= cnt; j += 8) {
            int cc[8]; float vv[8];
            #pragma unroll
            for (int q = 0; q < 8; q++) {
                cc[q] = __shfl_sync(0xffffffffu, c, j + q);
                vv[q] = __shfl_sync(0xffffffffu, v, j + q);
            }
            uint2 raw[8];
            #pragma unroll
            for (int q = 0; q < 8; q++)
                raw[q] = ((const uint2*)(g_fh16 + (size_t)cc[q] * D))[lane];
            #pragma unroll
            for (int q = 0; q < 8; q++) {
                float2 f0 = __half22float2(*(__half2*)&raw[q].x);
                float2 f1 = __half22float2(*(__half2*)&raw[q].y);
                acc.x += vv[q] * f0.x; acc.y += vv[q] * f0.y;
                acc.z += vv[q] * f1.x; acc.w += vv[q] * f1.y;
            }
        }
        for (; j < cnt; j++) {
            int   cj = __shfl_sync(0xffffffffu, c, j);
            float vj = __shfl_sync(0xffffffffu, v, j);
            uint2 raw = ((const uint2*)(g_fh16 + (size_t)cj * D))[lane];
            float2 f0 = __half22float2(*(__half2*)&raw.x);
            float2 f1 = __half22float2(*(__half2*)&raw.y);
            acc.x += vj * f0.x; acc.y += vj * f0.y;
            acc.z += vj * f1.x; acc.w += vj * f1.y;
        }
    }
    ((float4*)(g_Lx + (size_t)r * D))[lane] = acc;
}

// ---------------------------------------------------------------------------
// Tensor-core dual-GEMM via mma.sync (bf16x3 split) + bias + leaky + L2-norm.
// Also refreshes the fp16 gather plane with the new features.
// ---------------------------------------------------------------------------
__global__ void __launch_bounds__(512, 1) k_gemm_mma(const float* __restrict__ blin,
                                                     const float* __restrict__ bint,
                                                     int layer) {
    extern __shared__ char dsm[];
    __shared__ float sPart[128][4];

    char* sAh = dsm;
    char* sAm = dsm + TILE_B;
    char* sBh = dsm + 2 * TILE_B;
    char* sBm = dsm + 3 * TILE_B;
    uint32_t uAh = smem_u32(sAh);
    uint32_t uAm = uAh + TILE_B;
    uint32_t uBh = uAh + 2 * TILE_B;
    uint32_t uBm = uAh + 3 * TILE_B;

    int tid = threadIdx.x;
    int wid = tid >> 5;
    int lane = tid & 31;
    int rbase = blockIdx.x * 128;
    int wm = wid & 3, wn = wid >> 2;
    int m0 = wm * 32, n0 = wn * 32;
    int g = lane >> 2, t = lane & 3;

    float c[2][4][4];
    #pragma unroll
    for (int j = 0; j < 4; j++) {
        int col0 = n0 + j * 8 + 2 * t;
        float b0 = blin[(size_t)layer * D + col0] + bint[(size_t)layer * D + col0];
        float b1 = blin[(size_t)layer * D + col0 + 1] + bint[(size_t)layer * D + col0 + 1];
        #pragma unroll
        for (int mt = 0; mt < 2; mt++) {
            c[mt][j][0] = b0; c[mt][j][1] = b1;
            c[mt][j][2] = b0; c[mt][j][3] = b1;
        }
    }

    int aRow = m0 + (lane & 15);
    uint32_t aOff0 = (uint32_t)(aRow * TPITCH_B + (lane >> 4) * 16);
    uint32_t aOff1 = aOff0 + 16 * TPITCH_B;
    int bRow = n0 + ((lane >> 4) << 3) + (lane & 7);
    uint32_t bOff0 = (uint32_t)(bRow * TPITCH_B + ((lane >> 3) & 1) * 16);
    uint32_t bOff1 = bOff0 + 16 * TPITCH_B;

    #pragma unroll 1
    for (int phase = 0; phase < 2; phase++) {
        for (int gg = tid; gg < 2048; gg += 512) {
            int m = gg >> 4;
            int kg = (gg & 15) << 3;
            int r = rbase + m;
            float x[8];
            if (r < NTOT) {
                const float4* lp4 = (const float4*)(g_Lx + (size_t)r * D + kg);
                const float4* fp4 = (const float4*)(g_final + (size_t)r * FD + (size_t)layer * D + kg);
                float4 l0 = lp4[0], l1 = lp4[1];
                float4 f0 = fp4[0], f1 = fp4[1];
                if (phase == 0) {
                    x[0] = l0.x + f0.x; x[1] = l0.y + f0.y; x[2] = l0.z + f0.z; x[3] = l0.w + f0.w;
                    x[4] = l1.x + f1.x; x[5] = l1.y + f1.y; x[6] = l1.z + f1.z; x[7] = l1.w + f1.w;
                } else {
                    x[0] = l0.x * f0.x; x[1] = l0.y * f0.y; x[2] = l0.z * f0.z; x[3] = l0.w * f0.w;
                    x[4] = l1.x * f1.x; x[5] = l1.y * f1.y; x[6] = l1.z * f1.z; x[7] = l1.w * f1.w;
                }
            } else {
                #pragma unroll
                for (int jq = 0; jq < 8; jq++) x[jq] = 0.f;
            }
            uint32_t hp[4], mp[4];
            #pragma unroll
            for (int jq = 0; jq < 4; jq++) {
                float a0 = x[2 * jq], a1 = x[2 * jq + 1];
                __nv_bfloat16 h0 = __float2bfloat16(a0);
                __nv_bfloat16 h1 = __float2bfloat16(a1);
                __nv_bfloat16 mm0 = __float2bfloat16(a0 - __bfloat162float(h0));
                __nv_bfloat16 mm1 = __float2bfloat16(a1 - __bfloat162float(h1));
                hp[jq] = pack2(h0, h1);
                mp[jq] = pack2(mm0, mm1);
            }
            int off = m * TPITCH_B + kg * 2;
            *(uint4*)(sAh + off) = make_uint4(hp[0], hp[1], hp[2], hp[3]);
            *(uint4*)(sAm + off) = make_uint4(mp[0], mp[1], mp[2], mp[3]);
        }
        {
            const uint32_t* srcH = g_wimg + ((size_t)(layer * 2 + phase) * 2 + 0) * 8192;
            const uint32_t* srcM = g_wimg + ((size_t)(layer * 2 + phase) * 2 + 1) * 8192;
            for (int i = tid; i < 2048; i += 512) {
                int n = i >> 4;
                int jj = i & 15;
                int off = n * TPITCH_B + jj * 16;
                *(uint4*)(sBh + off) = ((const uint4*)(srcH + n * 64))[jj];
                *(uint4*)(sBm + off) = ((const uint4*)(srcM + n * 64))[jj];
            }
        }
        __syncthreads();

        #pragma unroll
        for (int ks = 0; ks < 8; ks++) {
            uint32_t kb = (uint32_t)(ks * 32);
            uint32_t ah[2][4], am[2][4], bh[2][4], bm[2][4];
            ldsm4(ah[0], uAh + aOff0 + kb);
            ldsm4(ah[1], uAh + aOff1 + kb);
            ldsm4(am[0], uAm + aOff0 + kb);
            ldsm4(am[1], uAm + aOff1 + kb);
            ldsm4(bh[0], uBh + bOff0 + kb);
            ldsm4(bh[1], uBh + bOff1 + kb);
            ldsm4(bm[0], uBm + bOff0 + kb);
            ldsm4(bm[1], uBm + bOff1 + kb);
            #pragma unroll
            for (int mt = 0; mt < 2; mt++) {
                #pragma unroll
                for (int j = 0; j < 4; j++) {
                    uint32_t bh0 = bh[j >> 1][(j & 1) * 2], bh1 = bh[j >> 1][(j & 1) * 2 + 1];
                    uint32_t bm0 = bm[j >> 1][(j & 1) * 2], bm1 = bm[j >> 1][(j & 1) * 2 + 1];
                    mma16816(c[mt][j], ah[mt], bh0, bh1);
                    mma16816(c[mt][j], ah[mt], bm0, bm1);
                    mma16816(c[mt][j], am[mt], bh0, bh1);
                }
            }
        }
        __syncthreads();
    }

    // ---- Epilogue ----
    #pragma unroll
    for (int mt = 0; mt < 2; mt++)
        #pragma unroll
        for (int j = 0; j < 4; j++)
            #pragma unroll
            for (int q = 0; q < 4; q++) {
                float v = c[mt][j][q];
                c[mt][j][q] = v > 0.f ? v : 0.01f * v;
            }

    float ss[2][2] = {{0.f, 0.f}, {0.f, 0.f}};
    #pragma unroll
    for (int mt = 0; mt < 2; mt++)
        #pragma unroll
        for (int j = 0; j < 4; j++) {
            ss[mt][0] += c[mt][j][0] * c[mt][j][0] + c[mt][j][1] * c[mt][j][1];
            ss[mt][1] += c[mt][j][2] * c[mt][j][2] + c[mt][j][3] * c[mt][j][3];
        }
    #pragma unroll
    for (int o = 1; o <= 2; o <<= 1) {
        #pragma unroll
        for (int mt = 0; mt < 2; mt++) {
            ss[mt][0] += __shfl_xor_sync(0xffffffffu, ss[mt][0], o);
            ss[mt][1] += __shfl_xor_sync(0xffffffffu, ss[mt][1], o);
        }
    }
    if (t == 0) {
        #pragma unroll
        for (int mt = 0; mt < 2; mt++) {
            sPart[m0 + mt * 16 + g][wn] = ss[mt][0];
            sPart[m0 + mt * 16 + g + 8][wn] = ss[mt][1];
        }
    }
    __syncthreads();

    #pragma unroll
    for (int mt = 0; mt < 2; mt++) {
        #pragma unroll
        for (int h = 0; h < 2; h++) {
            int row = m0 + mt * 16 + g + h * 8;
            float tot = sPart[row][0] + sPart[row][1] + sPart[row][2] + sPart[row][3];
            float scale = 1.0f / fmaxf(sqrtf(tot), 1e-12f);
            int rg = rbase + row;
            if (rg < NTOT) {
                float* dst = g_final + (size_t)rg * FD + (size_t)(layer + 1) * D;
                __half* dh = g_fh16 + (size_t)rg * D;
                #pragma unroll
                for (int j = 0; j < 4; j++) {
                    int col0 = n0 + j * 8 + 2 * t;
                    float v0 = c[mt][j][h * 2] * scale;
                    float v1 = c[mt][j][h * 2 + 1] * scale;
                    *(float2*)(dst + col0) = make_float2(v0, v1);
                    __half2 hv = __floats2half2_rn(v0, v1);
                    *(uint32_t*)(dh + col0) = *(uint32_t*)&hv;
                }
            }
        }
    }
}

// ---------------------------------------------------------------------------
// Final dot
// ---------------------------------------------------------------------------
__global__ void k_dot(const int* __restrict__ uIdx, const int* __restrict__ iIdx,
                      float* __restrict__ out) {
    int b = blockIdx.x * (blockDim.x >> 5) + (threadIdx.x >> 5);
    if (b >= BATCH) return;
    int lane = threadIdx.x & 31;
    int u = uIdx[b];
    int it = iIdx[b] + NUM_USERS;
    const float4* pu = (const float4*)(g_final + (size_t)u * FD);
    const float4* pi = (const float4*)(g_final + (size_t)it * FD);
    float s = 0.f;
    #pragma unroll
    for (int q = 0; q < 4; q++) {
        float4 a = pu[lane + 32 * q];
        float4 c = pi[lane + 32 * q];
        s += a.x * c.x + a.y * c.y + a.z * c.z + a.w * c.w;
    }
    #pragma unroll
    for (int o = 16; o > 0; o >>= 1)
        s += __shfl_xor_sync(0xffffffffu, s, o);
    if (lane == 0) out[b] = s;
}

// ---------------------------------------------------------------------------
extern "C" void kernel_launch(void* const* d_in, const int* in_sizes, int n_in,
                              void* d_out, int out_size) {
    const int*   userIdx = (const int*)d_in[0];
    const int*   itemIdx = (const int*)d_in[1];
    const int*   rows    = (const int*)d_in[2];
    const int*   cols    = (const int*)d_in[3];
    const float* vals    = (const float*)d_in[4];
    const float* uE      = (const float*)d_in[5];
    const float* iE      = (const float*)d_in[6];
    const float* Wlin    = (const float*)d_in[7];
    const float* blin    = (const float*)d_in[8];
    const float* Wint    = (const float*)d_in[9];
    const float* bint    = (const float*)d_in[10];
    float* out = (float*)d_out;

    const int smem_mma = 4 * TILE_B;  // 139264 B
    cudaFuncSetAttribute(k_gemm_mma, cudaFuncAttributeMaxDynamicSharedMemorySize, smem_mma);

    const int vec_total = NTOT * (D / 4);
    k_init<<<(vec_total + 255) / 256, 256>>>(uE, iE);
    k_wsplit<<<(3 * 2 * 128 * 64 + 255) / 256, 256>>>(Wlin, Wint);

    // CSR build (once per launch)
    k_zero_cnt<<<(NTOT + 255) / 256, 256>>>();
    k_count<<<(NNZ + 255) / 256, 256>>>(rows);
    k_scan1<<<SCAN_NB, 256>>>();
    k_scan2<<<1, 128>>>();
    k_scan3<<<(NTOT + 255) / 256, 256>>>();
    k_scatter<<<(NNZ + 255) / 256, 256>>>(rows, cols, vals);

    for (int l = 0; l < NLAYERS; l++) {
        k_spmm_h<<<(NTOT + 7) / 8, 256>>>();
        k_gemm_mma<<<(NTOT + 127) / 128, 512, smem_mma>>>(blin, bint, l);
    }

    k_dot<<<(BATCH + 7) / 8, 256>>>(userIdx, itemIdx, out);
}

// round 7
// speedup vs baseline: 1.0786x; 1.0786x over previous
#include <cuda_runtime.h>
#include <cuda_bf16.h>
#include <cstdint>

#define NUM_USERS 30000
#define NUM_ITEMS 70000
#define NTOT      100000
#define D         128
#define NNZ       1000000
#define NLAYERS   3
#define BATCH     16384
#define FD        512   // D * (1 + NLAYERS)

#define SCAN_BS   1024
#define SCAN_NB   ((NTOT + SCAN_BS - 1) / SCAN_BS)  // 98

// Scratch (no cudaMalloc allowed)
__device__ float  g_final[(size_t)NTOT * FD];
__device__ float  g_Lx[(size_t)NTOT * D];
__device__ int    g_cnt[NTOT];
__device__ int    g_start[NTOT + 1];
__device__ int    g_cursor[NTOT];
__device__ int    g_ecol[NNZ];
__device__ float  g_eval[NNZ];
__device__ int    g_bsum[SCAN_NB];
__device__ int    g_boff[SCAN_NB];
// Pre-split, pre-transposed weight images: per (layer, phase{lin,int}, split{hi,mid})
__device__ uint32_t g_wimg[3 * 2 * 2 * 8192];

// ======================= mma.sync helpers =======================
__device__ __forceinline__ uint32_t smem_u32(const void* p) {
    uint32_t a;
    asm("{ .reg .u64 t; cvta.to.shared.u64 t, %1; cvt.u32.u64 %0, t; }" : "=r"(a) : "l"(p));
    return a;
}
__device__ __forceinline__ void ldsm4(uint32_t* r, uint32_t addr) {
    asm volatile("ldmatrix.sync.aligned.m8n8.x4.shared.b16 {%0,%1,%2,%3}, [%4];"
                 : "=r"(r[0]), "=r"(r[1]), "=r"(r[2]), "=r"(r[3]) : "r"(addr));
}
__device__ __forceinline__ void mma16816(float* d, const uint32_t* a, uint32_t b0, uint32_t b1) {
    asm volatile(
        "mma.sync.aligned.m16n8k16.row.col.f32.bf16.bf16.f32 "
        "{%0,%1,%2,%3}, {%4,%5,%6,%7}, {%8,%9}, {%0,%1,%2,%3};"
        : "+f"(d[0]), "+f"(d[1]), "+f"(d[2]), "+f"(d[3])
        : "r"(a[0]), "r"(a[1]), "r"(a[2]), "r"(a[3]), "r"(b0), "r"(b1));
}
__device__ __forceinline__ uint32_t pack2(__nv_bfloat16 lo, __nv_bfloat16 hi) {
    return ((uint32_t)__bfloat16_as_ushort(hi) << 16) | (uint32_t)__bfloat16_as_ushort(lo);
}

#define TPITCH_B 272
#define TILE_B   (128 * TPITCH_B)   // 34816

// ---------------------------------------------------------------------------
// Init: features slice 0 + zero g_cnt (fused)
// ---------------------------------------------------------------------------
__global__ void k_init(const float* __restrict__ uE, const float* __restrict__ iE) {
    int idx = blockIdx.x * blockDim.x + threadIdx.x;
    const int total = NTOT * (D / 4);
    if (idx < total) {
        int r = idx >> 5;
        int q = idx & 31;
        float4 v = (r < NUM_USERS)
            ? ((const float4*)uE)[(size_t)r * (D / 4) + q]
            : ((const float4*)iE)[(size_t)(r - NUM_USERS) * (D / 4) + q];
        ((float4*)g_final)[(size_t)r * (FD / 4) + q] = v;
    }
    if (idx < NTOT) g_cnt[idx] = 0;   // total (3.2M) >> NTOT, covered
}

// ---------------------------------------------------------------------------
// Weight split/transpose precompute (once). B[n][k] = W[k][n], hi/mid bf16.
// ---------------------------------------------------------------------------
__global__ void k_wsplit(const float* __restrict__ Wlin, const float* __restrict__ Wint) {
    int idx = blockIdx.x * blockDim.x + threadIdx.x;
    const int total = 3 * 2 * 128 * 64;
    if (idx >= total) return;
    int k2 = idx & 63;
    int n  = (idx >> 6) & 127;
    int lp = idx >> 13;
    int p  = lp & 1;
    int l  = lp >> 1;
    int k  = k2 * 2;
    const float* W = (p ? Wint : Wlin) + (size_t)l * D * D;
    float w0 = W[(size_t)k * 128 + n];
    float w1 = W[(size_t)(k + 1) * 128 + n];
    __nv_bfloat16 h0 = __float2bfloat16(w0);
    __nv_bfloat16 h1 = __float2bfloat16(w1);
    __nv_bfloat16 m0 = __float2bfloat16(w0 - __bfloat162float(h0));
    __nv_bfloat16 m1 = __float2bfloat16(w1 - __bfloat162float(h1));
    int baseH = ((l * 2 + p) * 2 + 0) * 8192;
    int baseM = ((l * 2 + p) * 2 + 1) * 8192;
    g_wimg[baseH + n * 64 + k2] = pack2(h0, h1);
    g_wimg[baseM + n * 64 + k2] = pack2(m0, m1);
}

// ---------------------------------------------------------------------------
// CSR build
// ---------------------------------------------------------------------------
__global__ void k_count(const int* __restrict__ rows) {
    int e = blockIdx.x * blockDim.x + threadIdx.x;
    if (e < NNZ) atomicAdd(&g_cnt[rows[e]], 1);
}
__global__ void k_scan1() {
    __shared__ int wsum[8];
    int t = threadIdx.x;
    int base = blockIdx.x * SCAN_BS + t * 4;
    int c0 = 0, c1 = 0, c2 = 0, c3 = 0;
    if (base + 3 < NTOT) {
        int4 c = *(const int4*)(g_cnt + base);
        c0 = c.x; c1 = c.y; c2 = c.z; c3 = c.w;
    } else {
        if (base + 0 < NTOT) c0 = g_cnt[base + 0];
        if (base + 1 < NTOT) c1 = g_cnt[base + 1];
        if (base + 2 < NTOT) c2 = g_cnt[base + 2];
        if (base + 3 < NTOT) c3 = g_cnt[base + 3];
    }
    int tot = c0 + c1 + c2 + c3;
    int inc = tot;
    #pragma unroll
    for (int d = 1; d < 32; d <<= 1) {
        int v = __shfl_up_sync(0xffffffffu, inc, d);
        if ((t & 31) >= d) inc += v;
    }
    if ((t & 31) == 31) wsum[t >> 5] = inc;
    __syncthreads();
    if (t < 8) {
        int v = wsum[t];
        int wi = v;
        #pragma unroll
        for (int d = 1; d < 8; d <<= 1) {
            int u = __shfl_up_sync(0xffu, wi, d);
            if (t >= d) wi += u;
        }
        wsum[t] = wi - v;
        if (t == 7) g_bsum[blockIdx.x] = wi;
    }
    __syncthreads();
    int off = wsum[t >> 5] + (inc - tot);
    if (base + 0 < NTOT) g_start[base + 0] = off;
    if (base + 1 < NTOT) g_start[base + 1] = off + c0;
    if (base + 2 < NTOT) g_start[base + 2] = off + c0 + c1;
    if (base + 3 < NTOT) g_start[base + 3] = off + c0 + c1 + c2;
}
__global__ void k_scan2() {
    __shared__ int wsum[4];
    int t = threadIdx.x;
    int v = (t < SCAN_NB) ? g_bsum[t] : 0;
    int inc = v;
    #pragma unroll
    for (int d = 1; d < 32; d <<= 1) {
        int u = __shfl_up_sync(0xffffffffu, inc, d);
        if ((t & 31) >= d) inc += u;
    }
    if ((t & 31) == 31) wsum[t >> 5] = inc;
    __syncthreads();
    if (t < 4) {
        int w = wsum[t];
        int wi = w;
        #pragma unroll
        for (int d = 1; d < 4; d <<= 1) {
            int u = __shfl_up_sync(0xfu, wi, d);
            if (t >= d) wi += u;
        }
        wsum[t] = wi - w;
    }
    __syncthreads();
    if (t < SCAN_NB) g_boff[t] = wsum[t >> 5] + (inc - v);
    if (t == 0) g_start[NTOT] = NNZ;
}
__global__ void k_scan3() {
    int i = blockIdx.x * blockDim.x + threadIdx.x;
    if (i >= NTOT) return;
    int s = g_start[i] + g_boff[i / SCAN_BS];
    g_start[i] = s;
    g_cursor[i] = s;
}
__global__ void k_scatter(const int* __restrict__ rows, const int* __restrict__ cols,
                          const float* __restrict__ vals) {
    int e = blockIdx.x * blockDim.x + threadIdx.x;
    if (e >= NNZ) return;
    int p = atomicAdd(&g_cursor[rows[e]], 1);
    g_ecol[p] = cols[e];
    g_eval[p] = vals[e];
}

// ---------------------------------------------------------------------------
// SpMM gather (round-5 proven fp32 version)
// ---------------------------------------------------------------------------
__global__ void k_spmm_csr(int layer) {
    int r = blockIdx.x * (blockDim.x >> 5) + (threadIdx.x >> 5);
    if (r >= NTOT) return;
    int lane = threadIdx.x & 31;
    int s = g_start[r];
    int e = g_start[r + 1];
    const float* fb = g_final + (size_t)layer * D;
    float4 acc = make_float4(0.f, 0.f, 0.f, 0.f);
    for (int base = s; base < e; base += 32) {
        int idx = base + lane;
        int c = 0; float v = 0.f;
        if (idx < e) { c = g_ecol[idx]; v = g_eval[idx]; }
        int cnt = min(32, e - base);
        int j = 0;
        for (; j + 4 <= cnt; j += 4) {
            int   c0 = __shfl_sync(0xffffffffu, c, j + 0);
            int   c1 = __shfl_sync(0xffffffffu, c, j + 1);
            int   c2 = __shfl_sync(0xffffffffu, c, j + 2);
            int   c3 = __shfl_sync(0xffffffffu, c, j + 3);
            float v0 = __shfl_sync(0xffffffffu, v, j + 0);
            float v1 = __shfl_sync(0xffffffffu, v, j + 1);
            float v2 = __shfl_sync(0xffffffffu, v, j + 2);
            float v3 = __shfl_sync(0xffffffffu, v, j + 3);
            float4 x0 = ((const float4*)(fb + (size_t)c0 * FD))[lane];
            float4 x1 = ((const float4*)(fb + (size_t)c1 * FD))[lane];
            float4 x2 = ((const float4*)(fb + (size_t)c2 * FD))[lane];
            float4 x3 = ((const float4*)(fb + (size_t)c3 * FD))[lane];
            acc.x += v0 * x0.x + v1 * x1.x + v2 * x2.x + v3 * x3.x;
            acc.y += v0 * x0.y + v1 * x1.y + v2 * x2.y + v3 * x3.y;
            acc.z += v0 * x0.z + v1 * x1.z + v2 * x2.z + v3 * x3.z;
            acc.w += v0 * x0.w + v1 * x1.w + v2 * x2.w + v3 * x3.w;
        }
        for (; j < cnt; j++) {
            int   cj = __shfl_sync(0xffffffffu, c, j);
            float vj = __shfl_sync(0xffffffffu, v, j);
            float4 x = ((const float4*)(fb + (size_t)cj * FD))[lane];
            acc.x += vj * x.x; acc.y += vj * x.y;
            acc.z += vj * x.z; acc.w += vj * x.w;
        }
    }
    ((float4*)(g_Lx + (size_t)r * D))[lane] = acc;
}

// ---------------------------------------------------------------------------
// Tensor-core dual-GEMM via mma.sync (bf16x3 split), single A-pass (6 tiles):
//   sSh/sSm = split(Lx + f), sPh/sPm = split(Lx * f), sBh/sBm = W images.
// Phase0: A=sS*, B=Wlin. Phase1: A=sP*, B=Wint. fp32 accum persists.
// ---------------------------------------------------------------------------
__global__ void __launch_bounds__(512, 1) k_gemm_mma(const float* __restrict__ blin,
                                                     const float* __restrict__ bint,
                                                     int layer) {
    extern __shared__ char dsm[];
    __shared__ float sPart[128][4];

    char* sSh = dsm;
    char* sSm = dsm + TILE_B;
    char* sPh = dsm + 2 * TILE_B;
    char* sPm = dsm + 3 * TILE_B;
    char* sBh = dsm + 4 * TILE_B;
    char* sBm = dsm + 5 * TILE_B;
    uint32_t uBase = smem_u32(dsm);
    uint32_t uBh = uBase + 4 * TILE_B;
    uint32_t uBm = uBase + 5 * TILE_B;

    int tid = threadIdx.x;
    int wid = tid >> 5;
    int lane = tid & 31;
    int rbase = blockIdx.x * 128;
    int wm = wid & 3, wn = wid >> 2;
    int m0 = wm * 32, n0 = wn * 32;
    int g = lane >> 2, t = lane & 3;

    float c[2][4][4];
    #pragma unroll
    for (int j = 0; j < 4; j++) {
        int col0 = n0 + j * 8 + 2 * t;
        float b0 = blin[(size_t)layer * D + col0] + bint[(size_t)layer * D + col0];
        float b1 = blin[(size_t)layer * D + col0 + 1] + bint[(size_t)layer * D + col0 + 1];
        #pragma unroll
        for (int mt = 0; mt < 2; mt++) {
            c[mt][j][0] = b0; c[mt][j][1] = b1;
            c[mt][j][2] = b0; c[mt][j][3] = b1;
        }
    }

    int aRow = m0 + (lane & 15);
    uint32_t aOff0 = (uint32_t)(aRow * TPITCH_B + (lane >> 4) * 16);
    uint32_t aOff1 = aOff0 + 16 * TPITCH_B;
    int bRow = n0 + ((lane >> 4) << 3) + (lane & 7);
    uint32_t bOff0 = (uint32_t)(bRow * TPITCH_B + ((lane >> 3) & 1) * 16);
    uint32_t bOff1 = bOff0 + 16 * TPITCH_B;

    // ---- Single A fill: all four A tiles ----
    for (int gg = tid; gg < 2048; gg += 512) {
        int m = gg >> 4;
        int kg = (gg & 15) << 3;
        int r = rbase + m;
        float s[8], p[8];
        if (r < NTOT) {
            const float4* lp4 = (const float4*)(g_Lx + (size_t)r * D + kg);
            const float4* fp4 = (const float4*)(g_final + (size_t)r * FD + (size_t)layer * D + kg);
            float4 l0 = lp4[0], l1 = lp4[1];
            float4 f0 = fp4[0], f1 = fp4[1];
            s[0] = l0.x + f0.x; s[1] = l0.y + f0.y; s[2] = l0.z + f0.z; s[3] = l0.w + f0.w;
            s[4] = l1.x + f1.x; s[5] = l1.y + f1.y; s[6] = l1.z + f1.z; s[7] = l1.w + f1.w;
            p[0] = l0.x * f0.x; p[1] = l0.y * f0.y; p[2] = l0.z * f0.z; p[3] = l0.w * f0.w;
            p[4] = l1.x * f1.x; p[5] = l1.y * f1.y; p[6] = l1.z * f1.z; p[7] = l1.w * f1.w;
        } else {
            #pragma unroll
            for (int jq = 0; jq < 8; jq++) { s[jq] = 0.f; p[jq] = 0.f; }
        }
        uint32_t sh[4], sm[4], ph[4], pm[4];
        #pragma unroll
        for (int jq = 0; jq < 4; jq++) {
            float a0 = s[2 * jq], a1 = s[2 * jq + 1];
            __nv_bfloat16 h0 = __float2bfloat16(a0);
            __nv_bfloat16 h1 = __float2bfloat16(a1);
            sh[jq] = pack2(h0, h1);
            sm[jq] = pack2(__float2bfloat16(a0 - __bfloat162float(h0)),
                           __float2bfloat16(a1 - __bfloat162float(h1)));
            float b0 = p[2 * jq], b1 = p[2 * jq + 1];
            __nv_bfloat16 g0 = __float2bfloat16(b0);
            __nv_bfloat16 g1 = __float2bfloat16(b1);
            ph[jq] = pack2(g0, g1);
            pm[jq] = pack2(__float2bfloat16(b0 - __bfloat162float(g0)),
                           __float2bfloat16(b1 - __bfloat162float(g1)));
        }
        int off = m * TPITCH_B + kg * 2;
        *(uint4*)(sSh + off) = make_uint4(sh[0], sh[1], sh[2], sh[3]);
        *(uint4*)(sSm + off) = make_uint4(sm[0], sm[1], sm[2], sm[3]);
        *(uint4*)(sPh + off) = make_uint4(ph[0], ph[1], ph[2], ph[3]);
        *(uint4*)(sPm + off) = make_uint4(pm[0], pm[1], pm[2], pm[3]);
    }

    #pragma unroll 1
    for (int phase = 0; phase < 2; phase++) {
        if (phase == 1) __syncthreads();  // phase0 B reads done before overwrite
        {
            const uint32_t* srcH = g_wimg + ((size_t)(layer * 2 + phase) * 2 + 0) * 8192;
            const uint32_t* srcM = g_wimg + ((size_t)(layer * 2 + phase) * 2 + 1) * 8192;
            for (int i = tid; i < 2048; i += 512) {
                int n = i >> 4;
                int jj = i & 15;
                int off = n * TPITCH_B + jj * 16;
                *(uint4*)(sBh + off) = ((const uint4*)(srcH + n * 64))[jj];
                *(uint4*)(sBm + off) = ((const uint4*)(srcM + n * 64))[jj];
            }
        }
        __syncthreads();

        uint32_t uAh = uBase + (phase == 0 ? 0 : 2 * TILE_B);
        uint32_t uAm = uAh + TILE_B;

        #pragma unroll
        for (int ks = 0; ks < 8; ks++) {
            uint32_t kb = (uint32_t)(ks * 32);
            uint32_t ah[2][4], am[2][4], bh[2][4], bm[2][4];
            ldsm4(ah[0], uAh + aOff0 + kb);
            ldsm4(ah[1], uAh + aOff1 + kb);
            ldsm4(am[0], uAm + aOff0 + kb);
            ldsm4(am[1], uAm + aOff1 + kb);
            ldsm4(bh[0], uBh + bOff0 + kb);
            ldsm4(bh[1], uBh + bOff1 + kb);
            ldsm4(bm[0], uBm + bOff0 + kb);
            ldsm4(bm[1], uBm + bOff1 + kb);
            #pragma unroll
            for (int mt = 0; mt < 2; mt++) {
                #pragma unroll
                for (int j = 0; j < 4; j++) {
                    uint32_t bh0 = bh[j >> 1][(j & 1) * 2], bh1 = bh[j >> 1][(j & 1) * 2 + 1];
                    uint32_t bm0 = bm[j >> 1][(j & 1) * 2], bm1 = bm[j >> 1][(j & 1) * 2 + 1];
                    mma16816(c[mt][j], ah[mt], bh0, bh1);
                    mma16816(c[mt][j], ah[mt], bm0, bm1);
                    mma16816(c[mt][j], am[mt], bh0, bh1);
                }
            }
        }
    }

    // ---- Epilogue: leaky, cross-warp row norms, store ----
    #pragma unroll
    for (int mt = 0; mt < 2; mt++)
        #pragma unroll
        for (int j = 0; j < 4; j++)
            #pragma unroll
            for (int q = 0; q < 4; q++) {
                float v = c[mt][j][q];
                c[mt][j][q] = v > 0.f ? v : 0.01f * v;
            }

    float ss[2][2] = {{0.f, 0.f}, {0.f, 0.f}};
    #pragma unroll
    for (int mt = 0; mt < 2; mt++)
        #pragma unroll
        for (int j = 0; j < 4; j++) {
            ss[mt][0] += c[mt][j][0] * c[mt][j][0] + c[mt][j][1] * c[mt][j][1];
            ss[mt][1] += c[mt][j][2] * c[mt][j][2] + c[mt][j][3] * c[mt][j][3];
        }
    #pragma unroll
    for (int o = 1; o <= 2; o <<= 1) {
        #pragma unroll
        for (int mt = 0; mt < 2; mt++) {
            ss[mt][0] += __shfl_xor_sync(0xffffffffu, ss[mt][0], o);
            ss[mt][1] += __shfl_xor_sync(0xffffffffu, ss[mt][1], o);
        }
    }
    if (t == 0) {
        #pragma unroll
        for (int mt = 0; mt < 2; mt++) {
            sPart[m0 + mt * 16 + g][wn] = ss[mt][0];
            sPart[m0 + mt * 16 + g + 8][wn] = ss[mt][1];
        }
    }
    __syncthreads();

    #pragma unroll
    for (int mt = 0; mt < 2; mt++) {
        #pragma unroll
        for (int h = 0; h < 2; h++) {
            int row = m0 + mt * 16 + g + h * 8;
            float tot = sPart[row][0] + sPart[row][1] + sPart[row][2] + sPart[row][3];
            float scale = 1.0f / fmaxf(sqrtf(tot), 1e-12f);
            int rg = rbase + row;
            if (rg < NTOT) {
                float* dst = g_final + (size_t)rg * FD + (size_t)(layer + 1) * D;
                #pragma unroll
                for (int j = 0; j < 4; j++) {
                    int col0 = n0 + j * 8 + 2 * t;
                    *(float2*)(dst + col0) =
                        make_float2(c[mt][j][h * 2] * scale, c[mt][j][h * 2 + 1] * scale);
                }
            }
        }
    }
}

// ---------------------------------------------------------------------------
// Final dot
// ---------------------------------------------------------------------------
__global__ void k_dot(const int* __restrict__ uIdx, const int* __restrict__ iIdx,
                      float* __restrict__ out) {
    int b = blockIdx.x * (blockDim.x >> 5) + (threadIdx.x >> 5);
    if (b >= BATCH) return;
    int lane = threadIdx.x & 31;
    int u = uIdx[b];
    int it = iIdx[b] + NUM_USERS;
    const float4* pu = (const float4*)(g_final + (size_t)u * FD);
    const float4* pi = (const float4*)(g_final + (size_t)it * FD);
    float s = 0.f;
    #pragma unroll
    for (int q = 0; q < 4; q++) {
        float4 a = pu[lane + 32 * q];
        float4 c = pi[lane + 32 * q];
        s += a.x * c.x + a.y * c.y + a.z * c.z + a.w * c.w;
    }
    #pragma unroll
    for (int o = 16; o > 0; o >>= 1)
        s += __shfl_xor_sync(0xffffffffu, s, o);
    if (lane == 0) out[b] = s;
}

// ---------------------------------------------------------------------------
extern "C" void kernel_launch(void* const* d_in, const int* in_sizes, int n_in,
                              void* d_out, int out_size) {
    const int*   userIdx = (const int*)d_in[0];
    const int*   itemIdx = (const int*)d_in[1];
    const int*   rows    = (const int*)d_in[2];
    const int*   cols    = (const int*)d_in[3];
    const float* vals    = (const float*)d_in[4];
    const float* uE      = (const float*)d_in[5];
    const float* iE      = (const float*)d_in[6];
    const float* Wlin    = (const float*)d_in[7];
    const float* blin    = (const float*)d_in[8];
    const float* Wint    = (const float*)d_in[9];
    const float* bint    = (const float*)d_in[10];
    float* out = (float*)d_out;

    const int smem_mma = 6 * TILE_B;  // 208896 B
    cudaFuncSetAttribute(k_gemm_mma, cudaFuncAttributeMaxDynamicSharedMemorySize, smem_mma);

    const int vec_total = NTOT * (D / 4);
    k_init<<<(vec_total + 255) / 256, 256>>>(uE, iE);   // also zeroes g_cnt
    k_wsplit<<<(3 * 2 * 128 * 64 + 255) / 256, 256>>>(Wlin, Wint);

    // CSR build (once per launch)
    k_count<<<(NNZ + 255) / 256, 256>>>(rows);
    k_scan1<<<SCAN_NB, 256>>>();
    k_scan2<<<1, 128>>>();
    k_scan3<<<(NTOT + 255) / 256, 256>>>();
    k_scatter<<<(NNZ + 255) / 256, 256>>>(rows, cols, vals);

    for (int l = 0; l < NLAYERS; l++) {
        k_spmm_csr<<<(NTOT + 7) / 8, 256>>>(l);
        k_gemm_mma<<<(NTOT + 127) / 128, 512, smem_mma>>>(blin, bint, l);
    }

    k_dot<<<(BATCH + 7) / 8, 256>>>(userIdx, itemIdx, out);
}

// round 8
// speedup vs baseline: 1.4673x; 1.3604x over previous
#include <cuda_runtime.h>
#include <cuda_fp16.h>
#include <cstdint>

#define NUM_USERS 30000
#define NUM_ITEMS 70000
#define NTOT      100000
#define D         128
#define NNZ       1000000
#define NLAYERS   3
#define BATCH     16384
#define FD        512   // D * (1 + NLAYERS)

#define SCAN_BS   1024
#define SCAN_NB   ((NTOT + SCAN_BS - 1) / SCAN_BS)  // 98

// Scratch (no cudaMalloc allowed)
__device__ float  g_final[(size_t)NTOT * FD];
__device__ float  g_Lx[(size_t)NTOT * D];
__device__ int    g_cnt[NTOT];
__device__ int    g_start[NTOT + 1];
__device__ int    g_cursor[NTOT];
__device__ int    g_ecol[NNZ];
__device__ float  g_eval[NNZ];
__device__ int    g_bsum[SCAN_NB];
__device__ int    g_boff[SCAN_NB];
// Pre-transposed fp16 weight images: per (layer, phase{lin,int}): B[n][k]=W[k][n], 8192 u32 (32KB)
__device__ uint32_t g_wimg[3 * 2 * 8192];

// ======================= mma.sync helpers =======================
__device__ __forceinline__ uint32_t smem_u32(const void* p) {
    uint32_t a;
    asm("{ .reg .u64 t; cvta.to.shared.u64 t, %1; cvt.u32.u64 %0, t; }" : "=r"(a) : "l"(p));
    return a;
}
__device__ __forceinline__ void ldsm4(uint32_t* r, uint32_t addr) {
    asm volatile("ldmatrix.sync.aligned.m8n8.x4.shared.b16 {%0,%1,%2,%3}, [%4];"
                 : "=r"(r[0]), "=r"(r[1]), "=r"(r[2]), "=r"(r[3]) : "r"(addr));
}
__device__ __forceinline__ void mma16816h(float* d, const uint32_t* a, uint32_t b0, uint32_t b1) {
    asm volatile(
        "mma.sync.aligned.m16n8k16.row.col.f32.f16.f16.f32 "
        "{%0,%1,%2,%3}, {%4,%5,%6,%7}, {%8,%9}, {%0,%1,%2,%3};"
        : "+f"(d[0]), "+f"(d[1]), "+f"(d[2]), "+f"(d[3])
        : "r"(a[0]), "r"(a[1]), "r"(a[2]), "r"(a[3]), "r"(b0), "r"(b1));
}

#define TPITCH_B 272
#define TILE_B   (128 * TPITCH_B)   // 34816

// ---------------------------------------------------------------------------
// Init: features slice 0 + zero g_cnt (fused)
// ---------------------------------------------------------------------------
__global__ void k_init(const float* __restrict__ uE, const float* __restrict__ iE) {
    int idx = blockIdx.x * blockDim.x + threadIdx.x;
    const int total = NTOT * (D / 4);
    if (idx < total) {
        int r = idx >> 5;
        int q = idx & 31;
        float4 v = (r < NUM_USERS)
            ? ((const float4*)uE)[(size_t)r * (D / 4) + q]
            : ((const float4*)iE)[(size_t)(r - NUM_USERS) * (D / 4) + q];
        ((float4*)g_final)[(size_t)r * (FD / 4) + q] = v;
    }
    if (idx < NTOT) g_cnt[idx] = 0;
}

// ---------------------------------------------------------------------------
// Weight transpose+fp16 precompute (once). B[n][k] = W[k][n].
// ---------------------------------------------------------------------------
__global__ void k_wconv(const float* __restrict__ Wlin, const float* __restrict__ Wint) {
    int idx = blockIdx.x * blockDim.x + threadIdx.x;
    const int total = 3 * 2 * 128 * 64;
    if (idx >= total) return;
    int k2 = idx & 63;
    int n  = (idx >> 6) & 127;
    int lp = idx >> 13;
    int p  = lp & 1;
    int l  = lp >> 1;
    int k  = k2 * 2;
    const float* W = (p ? Wint : Wlin) + (size_t)l * D * D;
    __half2 h = __floats2half2_rn(W[(size_t)k * 128 + n], W[(size_t)(k + 1) * 128 + n]);
    g_wimg[(size_t)(l * 2 + p) * 8192 + n * 64 + k2] = *(uint32_t*)&h;
}

// ---------------------------------------------------------------------------
// CSR build
// ---------------------------------------------------------------------------
__global__ void k_count(const int* __restrict__ rows) {
    int e = blockIdx.x * blockDim.x + threadIdx.x;
    if (e < NNZ) atomicAdd(&g_cnt[rows[e]], 1);
}
__global__ void k_scan1() {
    __shared__ int wsum[8];
    int t = threadIdx.x;
    int base = blockIdx.x * SCAN_BS + t * 4;
    int c0 = 0, c1 = 0, c2 = 0, c3 = 0;
    if (base + 3 < NTOT) {
        int4 c = *(const int4*)(g_cnt + base);
        c0 = c.x; c1 = c.y; c2 = c.z; c3 = c.w;
    } else {
        if (base + 0 < NTOT) c0 = g_cnt[base + 0];
        if (base + 1 < NTOT) c1 = g_cnt[base + 1];
        if (base + 2 < NTOT) c2 = g_cnt[base + 2];
        if (base + 3 < NTOT) c3 = g_cnt[base + 3];
    }
    int tot = c0 + c1 + c2 + c3;
    int inc = tot;
    #pragma unroll
    for (int d = 1; d < 32; d <<= 1) {
        int v = __shfl_up_sync(0xffffffffu, inc, d);
        if ((t & 31) >= d) inc += v;
    }
    if ((t & 31) == 31) wsum[t >> 5] = inc;
    __syncthreads();
    if (t < 8) {
        int v = wsum[t];
        int wi = v;
        #pragma unroll
        for (int d = 1; d < 8; d <<= 1) {
            int u = __shfl_up_sync(0xffu, wi, d);
            if (t >= d) wi += u;
        }
        wsum[t] = wi - v;
        if (t == 7) g_bsum[blockIdx.x] = wi;
    }
    __syncthreads();
    int off = wsum[t >> 5] + (inc - tot);
    if (base + 0 < NTOT) g_start[base + 0] = off;
    if (base + 1 < NTOT) g_start[base + 1] = off + c0;
    if (base + 2 < NTOT) g_start[base + 2] = off + c0 + c1;
    if (base + 3 < NTOT) g_start[base + 3] = off + c0 + c1 + c2;
}
__global__ void k_scan2() {
    __shared__ int wsum[4];
    int t = threadIdx.x;
    int v = (t < SCAN_NB) ? g_bsum[t] : 0;
    int inc = v;
    #pragma unroll
    for (int d = 1; d < 32; d <<= 1) {
        int u = __shfl_up_sync(0xffffffffu, inc, d);
        if ((t & 31) >= d) inc += u;
    }
    if ((t & 31) == 31) wsum[t >> 5] = inc;
    __syncthreads();
    if (t < 4) {
        int w = wsum[t];
        int wi = w;
        #pragma unroll
        for (int d = 1; d < 4; d <<= 1) {
            int u = __shfl_up_sync(0xfu, wi, d);
            if (t >= d) wi += u;
        }
        wsum[t] = wi - w;
    }
    __syncthreads();
    if (t < SCAN_NB) g_boff[t] = wsum[t >> 5] + (inc - v);
    if (t == 0) g_start[NTOT] = NNZ;
}
__global__ void k_scan3() {
    int i = blockIdx.x * blockDim.x + threadIdx.x;
    if (i >= NTOT) return;
    int s = g_start[i] + g_boff[i / SCAN_BS];
    g_start[i] = s;
    g_cursor[i] = s;
}
__global__ void k_scatter(const int* __restrict__ rows, const int* __restrict__ cols,
                          const float* __restrict__ vals) {
    int e = blockIdx.x * blockDim.x + threadIdx.x;
    if (e >= NNZ) return;
    int p = atomicAdd(&g_cursor[rows[e]], 1);
    g_ecol[p] = cols[e];
    g_eval[p] = vals[e];
}

// ---------------------------------------------------------------------------
// SpMM gather (proven fp32 version)
// ---------------------------------------------------------------------------
__global__ void k_spmm_csr(int layer) {
    int r = blockIdx.x * (blockDim.x >> 5) + (threadIdx.x >> 5);
    if (r >= NTOT) return;
    int lane = threadIdx.x & 31;
    int s = g_start[r];
    int e = g_start[r + 1];
    const float* fb = g_final + (size_t)layer * D;
    float4 acc = make_float4(0.f, 0.f, 0.f, 0.f);
    for (int base = s; base < e; base += 32) {
        int idx = base + lane;
        int c = 0; float v = 0.f;
        if (idx < e) { c = g_ecol[idx]; v = g_eval[idx]; }
        int cnt = min(32, e - base);
        int j = 0;
        for (; j + 4 <= cnt; j += 4) {
            int   c0 = __shfl_sync(0xffffffffu, c, j + 0);
            int   c1 = __shfl_sync(0xffffffffu, c, j + 1);
            int   c2 = __shfl_sync(0xffffffffu, c, j + 2);
            int   c3 = __shfl_sync(0xffffffffu, c, j + 3);
            float v0 = __shfl_sync(0xffffffffu, v, j + 0);
            float v1 = __shfl_sync(0xffffffffu, v, j + 1);
            float v2 = __shfl_sync(0xffffffffu, v, j + 2);
            float v3 = __shfl_sync(0xffffffffu, v, j + 3);
            float4 x0 = ((const float4*)(fb + (size_t)c0 * FD))[lane];
            float4 x1 = ((const float4*)(fb + (size_t)c1 * FD))[lane];
            float4 x2 = ((const float4*)(fb + (size_t)c2 * FD))[lane];
            float4 x3 = ((const float4*)(fb + (size_t)c3 * FD))[lane];
            acc.x += v0 * x0.x + v1 * x1.x + v2 * x2.x + v3 * x3.x;
            acc.y += v0 * x0.y + v1 * x1.y + v2 * x2.y + v3 * x3.y;
            acc.z += v0 * x0.z + v1 * x1.z + v2 * x2.z + v3 * x3.z;
            acc.w += v0 * x0.w + v1 * x1.w + v2 * x2.w + v3 * x3.w;
        }
        for (; j < cnt; j++) {
            int   cj = __shfl_sync(0xffffffffu, c, j);
            float vj = __shfl_sync(0xffffffffu, v, j);
            float4 x = ((const float4*)(fb + (size_t)cj * FD))[lane];
            acc.x += vj * x.x; acc.y += vj * x.y;
            acc.z += vj * x.z; acc.w += vj * x.w;
        }
    }
    ((float4*)(g_Lx + (size_t)r * D))[lane] = acc;
}

// ---------------------------------------------------------------------------
// Tensor-core dual-GEMM via mma.sync, full fp16 (single-term), 3 smem tiles:
//   sS = fp16(Lx + f), sP = fp16(Lx * f), sB = W image (reloaded per phase).
// Phase0: A=sS, B=Wlin. Phase1: A=sP, B=Wint. fp32 accum persists.
// 102KB smem -> 2 CTAs/SM.
// ---------------------------------------------------------------------------
__global__ void __launch_bounds__(512) k_gemm_mma(const float* __restrict__ blin,
                                                  const float* __restrict__ bint,
                                                  int layer) {
    extern __shared__ char dsm[];
    __shared__ float sPart[128][4];

    char* sS = dsm;
    char* sP = dsm + TILE_B;
    char* sB = dsm + 2 * TILE_B;
    uint32_t uBase = smem_u32(dsm);
    uint32_t uB = uBase + 2 * TILE_B;

    int tid = threadIdx.x;
    int wid = tid >> 5;
    int lane = tid & 31;
    int rbase = blockIdx.x * 128;
    int wm = wid & 3, wn = wid >> 2;
    int m0 = wm * 32, n0 = wn * 32;
    int g = lane >> 2, t = lane & 3;

    float c[2][4][4];
    #pragma unroll
    for (int j = 0; j < 4; j++) {
        int col0 = n0 + j * 8 + 2 * t;
        float b0 = blin[(size_t)layer * D + col0] + bint[(size_t)layer * D + col0];
        float b1 = blin[(size_t)layer * D + col0 + 1] + bint[(size_t)layer * D + col0 + 1];
        #pragma unroll
        for (int mt = 0; mt < 2; mt++) {
            c[mt][j][0] = b0; c[mt][j][1] = b1;
            c[mt][j][2] = b0; c[mt][j][3] = b1;
        }
    }

    int aRow = m0 + (lane & 15);
    uint32_t aOff0 = (uint32_t)(aRow * TPITCH_B + (lane >> 4) * 16);
    uint32_t aOff1 = aOff0 + 16 * TPITCH_B;
    int bRow = n0 + ((lane >> 4) << 3) + (lane & 7);
    uint32_t bOff0 = (uint32_t)(bRow * TPITCH_B + ((lane >> 3) & 1) * 16);
    uint32_t bOff1 = bOff0 + 16 * TPITCH_B;

    // ---- Single A fill: both fp16 A tiles ----
    for (int gg = tid; gg < 2048; gg += 512) {
        int m = gg >> 4;
        int kg = (gg & 15) << 3;
        int r = rbase + m;
        uint32_t sv[4], pv[4];
        if (r < NTOT) {
            const float4* lp4 = (const float4*)(g_Lx + (size_t)r * D + kg);
            const float4* fp4 = (const float4*)(g_final + (size_t)r * FD + (size_t)layer * D + kg);
            float4 l0 = lp4[0], l1 = lp4[1];
            float4 f0 = fp4[0], f1 = fp4[1];
            __half2 h;
            h = __floats2half2_rn(l0.x + f0.x, l0.y + f0.y); sv[0] = *(uint32_t*)&h;
            h = __floats2half2_rn(l0.z + f0.z, l0.w + f0.w); sv[1] = *(uint32_t*)&h;
            h = __floats2half2_rn(l1.x + f1.x, l1.y + f1.y); sv[2] = *(uint32_t*)&h;
            h = __floats2half2_rn(l1.z + f1.z, l1.w + f1.w); sv[3] = *(uint32_t*)&h;
            h = __floats2half2_rn(l0.x * f0.x, l0.y * f0.y); pv[0] = *(uint32_t*)&h;
            h = __floats2half2_rn(l0.z * f0.z, l0.w * f0.w); pv[1] = *(uint32_t*)&h;
            h = __floats2half2_rn(l1.x * f1.x, l1.y * f1.y); pv[2] = *(uint32_t*)&h;
            h = __floats2half2_rn(l1.z * f1.z, l1.w * f1.w); pv[3] = *(uint32_t*)&h;
        } else {
            sv[0] = sv[1] = sv[2] = sv[3] = 0u;
            pv[0] = pv[1] = pv[2] = pv[3] = 0u;
        }
        int off = m * TPITCH_B + kg * 2;
        *(uint4*)(sS + off) = make_uint4(sv[0], sv[1], sv[2], sv[3]);
        *(uint4*)(sP + off) = make_uint4(pv[0], pv[1], pv[2], pv[3]);
    }

    #pragma unroll 1
    for (int phase = 0; phase < 2; phase++) {
        if (phase == 1) __syncthreads();  // phase0 B reads done before overwrite
        {
            const uint32_t* src = g_wimg + (size_t)(layer * 2 + phase) * 8192;
            for (int i = tid; i < 2048; i += 512) {
                int n = i >> 4;
                int jj = i & 15;
                *(uint4*)(sB + n * TPITCH_B + jj * 16) = ((const uint4*)(src + n * 64))[jj];
            }
        }
        __syncthreads();

        uint32_t uA = uBase + (phase == 0 ? 0 : TILE_B);

        #pragma unroll
        for (int ks = 0; ks < 8; ks++) {
            uint32_t kb = (uint32_t)(ks * 32);
            uint32_t a[2][4], b[2][4];
            ldsm4(a[0], uA + aOff0 + kb);
            ldsm4(a[1], uA + aOff1 + kb);
            ldsm4(b[0], uB + bOff0 + kb);
            ldsm4(b[1], uB + bOff1 + kb);
            #pragma unroll
            for (int mt = 0; mt < 2; mt++) {
                #pragma unroll
                for (int j = 0; j < 4; j++) {
                    mma16816h(c[mt][j], a[mt],
                              b[j >> 1][(j & 1) * 2], b[j >> 1][(j & 1) * 2 + 1]);
                }
            }
        }
    }

    // ---- Epilogue: leaky, cross-warp row norms, store ----
    #pragma unroll
    for (int mt = 0; mt < 2; mt++)
        #pragma unroll
        for (int j = 0; j < 4; j++)
            #pragma unroll
            for (int q = 0; q < 4; q++) {
                float v = c[mt][j][q];
                c[mt][j][q] = v > 0.f ? v : 0.01f * v;
            }

    float ss[2][2] = {{0.f, 0.f}, {0.f, 0.f}};
    #pragma unroll
    for (int mt = 0; mt < 2; mt++)
        #pragma unroll
        for (int j = 0; j < 4; j++) {
            ss[mt][0] += c[mt][j][0] * c[mt][j][0] + c[mt][j][1] * c[mt][j][1];
            ss[mt][1] += c[mt][j][2] * c[mt][j][2] + c[mt][j][3] * c[mt][j][3];
        }
    #pragma unroll
    for (int o = 1; o <= 2; o <<= 1) {
        #pragma unroll
        for (int mt = 0; mt < 2; mt++) {
            ss[mt][0] += __shfl_xor_sync(0xffffffffu, ss[mt][0], o);
            ss[mt][1] += __shfl_xor_sync(0xffffffffu, ss[mt][1], o);
        }
    }
    if (t == 0) {
        #pragma unroll
        for (int mt = 0; mt < 2; mt++) {
            sPart[m0 + mt * 16 + g][wn] = ss[mt][0];
            sPart[m0 + mt * 16 + g + 8][wn] = ss[mt][1];
        }
    }
    __syncthreads();

    #pragma unroll
    for (int mt = 0; mt < 2; mt++) {
        #pragma unroll
        for (int h = 0; h < 2; h++) {
            int row = m0 + mt * 16 + g + h * 8;
            float tot = sPart[row][0] + sPart[row][1] + sPart[row][2] + sPart[row][3];
            float scale = 1.0f / fmaxf(sqrtf(tot), 1e-12f);
            int rg = rbase + row;
            if (rg < NTOT) {
                float* dst = g_final + (size_t)rg * FD + (size_t)(layer + 1) * D;
                #pragma unroll
                for (int j = 0; j < 4; j++) {
                    int col0 = n0 + j * 8 + 2 * t;
                    *(float2*)(dst + col0) =
                        make_float2(c[mt][j][h * 2] * scale, c[mt][j][h * 2 + 1] * scale);
                }
            }
        }
    }
}

// ---------------------------------------------------------------------------
// Final dot
// ---------------------------------------------------------------------------
__global__ void k_dot(const int* __restrict__ uIdx, const int* __restrict__ iIdx,
                      float* __restrict__ out) {
    int b = blockIdx.x * (blockDim.x >> 5) + (threadIdx.x >> 5);
    if (b >= BATCH) return;
    int lane = threadIdx.x & 31;
    int u = uIdx[b];
    int it = iIdx[b] + NUM_USERS;
    const float4* pu = (const float4*)(g_final + (size_t)u * FD);
    const float4* pi = (const float4*)(g_final + (size_t)it * FD);
    float s = 0.f;
    #pragma unroll
    for (int q = 0; q < 4; q++) {
        float4 a = pu[lane + 32 * q];
        float4 c = pi[lane + 32 * q];
        s += a.x * c.x + a.y * c.y + a.z * c.z + a.w * c.w;
    }
    #pragma unroll
    for (int o = 16; o > 0; o >>= 1)
        s += __shfl_xor_sync(0xffffffffu, s, o);
    if (lane == 0) out[b] = s;
}

// ---------------------------------------------------------------------------
extern "C" void kernel_launch(void* const* d_in, const int* in_sizes, int n_in,
                              void* d_out, int out_size) {
    const int*   userIdx = (const int*)d_in[0];
    const int*   itemIdx = (const int*)d_in[1];
    const int*   rows    = (const int*)d_in[2];
    const int*   cols    = (const int*)d_in[3];
    const float* vals    = (const float*)d_in[4];
    const float* uE      = (const float*)d_in[5];
    const float* iE      = (const float*)d_in[6];
    const float* Wlin    = (const float*)d_in[7];
    const float* blin    = (const float*)d_in[8];
    const float* Wint    = (const float*)d_in[9];
    const float* bint    = (const float*)d_in[10];
    float* out = (float*)d_out;

    const int smem_mma = 3 * TILE_B;  // 104448 B -> 2 CTAs/SM
    cudaFuncSetAttribute(k_gemm_mma, cudaFuncAttributeMaxDynamicSharedMemorySize, smem_mma);

    const int vec_total = NTOT * (D / 4);
    k_init<<<(vec_total + 255) / 256, 256>>>(uE, iE);   // also zeroes g_cnt
    k_wconv<<<(3 * 2 * 128 * 64 + 255) / 256, 256>>>(Wlin, Wint);

    // CSR build (once per launch)
    k_count<<<(NNZ + 255) / 256, 256>>>(rows);
    k_scan1<<<SCAN_NB, 256>>>();
    k_scan2<<<1, 128>>>();
    k_scan3<<<(NTOT + 255) / 256, 256>>>();
    k_scatter<<<(NNZ + 255) / 256, 256>>>(rows, cols, vals);

    for (int l = 0; l < NLAYERS; l++) {
        k_spmm_csr<<<(NTOT + 7) / 8, 256>>>(l);
        k_gemm_mma<<<(NTOT + 127) / 128, 512, smem_mma>>>(blin, bint, l);
    }

    k_dot<<<(BATCH + 7) / 8, 256>>>(userIdx, itemIdx, out);
}

// round 9
// speedup vs baseline: 1.4768x; 1.0065x over previous
#include <cuda_runtime.h>
#include <cuda_fp16.h>
#include <cstdint>

#define NUM_USERS 30000
#define NUM_ITEMS 70000
#define NTOT      100000
#define D         128
#define NNZ       1000000
#define NLAYERS   3
#define BATCH     16384
#define FD        512   // D * (1 + NLAYERS)

#define SCAN_BS   1024
#define SCAN_NB   ((NTOT + SCAN_BS - 1) / SCAN_BS)  // 98

// Scratch (no cudaMalloc allowed)
__device__ float  g_final[(size_t)NTOT * FD];
__device__ float  g_Lx[(size_t)NTOT * D];
__device__ int    g_cnt[NTOT];
__device__ int    g_start[NTOT + 1];
__device__ int    g_cursor[NTOT];
__device__ int    g_ecol[NNZ];
__device__ float  g_eval[NNZ];
__device__ int    g_bsum[SCAN_NB];
__device__ int    g_boff[SCAN_NB];
// Pre-transposed fp16 weight images: per (layer, phase{lin,int}): B[n][k]=W[k][n], 8192 u32 (32KB)
__device__ uint32_t g_wimg[3 * 2 * 8192];

// ======================= mma.sync helpers =======================
__device__ __forceinline__ uint32_t smem_u32(const void* p) {
    uint32_t a;
    asm("{ .reg .u64 t; cvta.to.shared.u64 t, %1; cvt.u32.u64 %0, t; }" : "=r"(a) : "l"(p));
    return a;
}
__device__ __forceinline__ void ldsm4(uint32_t* r, uint32_t addr) {
    asm volatile("ldmatrix.sync.aligned.m8n8.x4.shared.b16 {%0,%1,%2,%3}, [%4];"
                 : "=r"(r[0]), "=r"(r[1]), "=r"(r[2]), "=r"(r[3]) : "r"(addr));
}
__device__ __forceinline__ void mma16816h(float* d, const uint32_t* a, uint32_t b0, uint32_t b1) {
    asm volatile(
        "mma.sync.aligned.m16n8k16.row.col.f32.f16.f16.f32 "
        "{%0,%1,%2,%3}, {%4,%5,%6,%7}, {%8,%9}, {%0,%1,%2,%3};"
        : "+f"(d[0]), "+f"(d[1]), "+f"(d[2]), "+f"(d[3])
        : "r"(a[0]), "r"(a[1]), "r"(a[2]), "r"(a[3]), "r"(b0), "r"(b1));
}

#define TPITCH_B 272
#define TILE_B   (128 * TPITCH_B)   // 34816

// ---------------------------------------------------------------------------
// Init: features slice 0 + zero g_cnt (fused)
// ---------------------------------------------------------------------------
__global__ void k_init(const float* __restrict__ uE, const float* __restrict__ iE) {
    int idx = blockIdx.x * blockDim.x + threadIdx.x;
    const int total = NTOT * (D / 4);
    if (idx < total) {
        int r = idx >> 5;
        int q = idx & 31;
        float4 v = (r < NUM_USERS)
            ? ((const float4*)uE)[(size_t)r * (D / 4) + q]
            : ((const float4*)iE)[(size_t)(r - NUM_USERS) * (D / 4) + q];
        ((float4*)g_final)[(size_t)r * (FD / 4) + q] = v;
    }
    if (idx < NTOT) g_cnt[idx] = 0;
}

// ---------------------------------------------------------------------------
// Weight transpose+fp16 precompute (once). B[n][k] = W[k][n].
// ---------------------------------------------------------------------------
__global__ void k_wconv(const float* __restrict__ Wlin, const float* __restrict__ Wint) {
    int idx = blockIdx.x * blockDim.x + threadIdx.x;
    const int total = 3 * 2 * 128 * 64;
    if (idx >= total) return;
    int k2 = idx & 63;
    int n  = (idx >> 6) & 127;
    int lp = idx >> 13;
    int p  = lp & 1;
    int l  = lp >> 1;
    int k  = k2 * 2;
    const float* W = (p ? Wint : Wlin) + (size_t)l * D * D;
    __half2 h = __floats2half2_rn(W[(size_t)k * 128 + n], W[(size_t)(k + 1) * 128 + n]);
    g_wimg[(size_t)(l * 2 + p) * 8192 + n * 64 + k2] = *(uint32_t*)&h;
}

// ---------------------------------------------------------------------------
// CSR build
// ---------------------------------------------------------------------------
__global__ void k_count(const int* __restrict__ rows) {
    int e = blockIdx.x * blockDim.x + threadIdx.x;
    if (e < NNZ) atomicAdd(&g_cnt[rows[e]], 1);
}
__global__ void k_scan1() {
    __shared__ int wsum[8];
    int t = threadIdx.x;
    int base = blockIdx.x * SCAN_BS + t * 4;
    int c0 = 0, c1 = 0, c2 = 0, c3 = 0;
    if (base + 3 < NTOT) {
        int4 c = *(const int4*)(g_cnt + base);
        c0 = c.x; c1 = c.y; c2 = c.z; c3 = c.w;
    } else {
        if (base + 0 < NTOT) c0 = g_cnt[base + 0];
        if (base + 1 < NTOT) c1 = g_cnt[base + 1];
        if (base + 2 < NTOT) c2 = g_cnt[base + 2];
        if (base + 3 < NTOT) c3 = g_cnt[base + 3];
    }
    int tot = c0 + c1 + c2 + c3;
    int inc = tot;
    #pragma unroll
    for (int d = 1; d < 32; d <<= 1) {
        int v = __shfl_up_sync(0xffffffffu, inc, d);
        if ((t & 31) >= d) inc += v;
    }
    if ((t & 31) == 31) wsum[t >> 5] = inc;
    __syncthreads();
    if (t < 8) {
        int v = wsum[t];
        int wi = v;
        #pragma unroll
        for (int d = 1; d < 8; d <<= 1) {
            int u = __shfl_up_sync(0xffu, wi, d);
            if (t >= d) wi += u;
        }
        wsum[t] = wi - v;
        if (t == 7) g_bsum[blockIdx.x] = wi;
    }
    __syncthreads();
    int off = wsum[t >> 5] + (inc - tot);
    if (base + 0 < NTOT) g_start[base + 0] = off;
    if (base + 1 < NTOT) g_start[base + 1] = off + c0;
    if (base + 2 < NTOT) g_start[base + 2] = off + c0 + c1;
    if (base + 3 < NTOT) g_start[base + 3] = off + c0 + c1 + c2;
}
__global__ void k_scan2() {
    __shared__ int wsum[4];
    int t = threadIdx.x;
    int v = (t < SCAN_NB) ? g_bsum[t] : 0;
    int inc = v;
    #pragma unroll
    for (int d = 1; d < 32; d <<= 1) {
        int u = __shfl_up_sync(0xffffffffu, inc, d);
        if ((t & 31) >= d) inc += u;
    }
    if ((t & 31) == 31) wsum[t >> 5] = inc;
    __syncthreads();
    if (t < 4) {
        int w = wsum[t];
        int wi = w;
        #pragma unroll
        for (int d = 1; d < 4; d <<= 1) {
            int u = __shfl_up_sync(0xfu, wi, d);
            if (t >= d) wi += u;
        }
        wsum[t] = wi - w;
    }
    __syncthreads();
    if (t < SCAN_NB) g_boff[t] = wsum[t >> 5] + (inc - v);
    if (t == 0) g_start[NTOT] = NNZ;
}
__global__ void k_scan3() {
    int i = blockIdx.x * blockDim.x + threadIdx.x;
    if (i >= NTOT) return;
    int s = g_start[i] + g_boff[i / SCAN_BS];
    g_start[i] = s;
    g_cursor[i] = s;
}
__global__ void k_scatter(const int* __restrict__ rows, const int* __restrict__ cols,
                          const float* __restrict__ vals) {
    int e = blockIdx.x * blockDim.x + threadIdx.x;
    if (e >= NNZ) return;
    int p = atomicAdd(&g_cursor[rows[e]], 1);
    g_ecol[p] = cols[e];
    g_eval[p] = vals[e];
}

// ---------------------------------------------------------------------------
// SpMM gather (proven fp32 version)
// ---------------------------------------------------------------------------
__global__ void k_spmm_csr(int layer) {
    int r = blockIdx.x * (blockDim.x >> 5) + (threadIdx.x >> 5);
    if (r >= NTOT) return;
    int lane = threadIdx.x & 31;
    int s = g_start[r];
    int e = g_start[r + 1];
    const float* fb = g_final + (size_t)layer * D;
    float4 acc = make_float4(0.f, 0.f, 0.f, 0.f);
    for (int base = s; base < e; base += 32) {
        int idx = base + lane;
        int c = 0; float v = 0.f;
        if (idx < e) { c = g_ecol[idx]; v = g_eval[idx]; }
        int cnt = min(32, e - base);
        int j = 0;
        for (; j + 4 <= cnt; j += 4) {
            int   c0 = __shfl_sync(0xffffffffu, c, j + 0);
            int   c1 = __shfl_sync(0xffffffffu, c, j + 1);
            int   c2 = __shfl_sync(0xffffffffu, c, j + 2);
            int   c3 = __shfl_sync(0xffffffffu, c, j + 3);
            float v0 = __shfl_sync(0xffffffffu, v, j + 0);
            float v1 = __shfl_sync(0xffffffffu, v, j + 1);
            float v2 = __shfl_sync(0xffffffffu, v, j + 2);
            float v3 = __shfl_sync(0xffffffffu, v, j + 3);
            float4 x0 = ((const float4*)(fb + (size_t)c0 * FD))[lane];
            float4 x1 = ((const float4*)(fb + (size_t)c1 * FD))[lane];
            float4 x2 = ((const float4*)(fb + (size_t)c2 * FD))[lane];
            float4 x3 = ((const float4*)(fb + (size_t)c3 * FD))[lane];
            acc.x += v0 * x0.x + v1 * x1.x + v2 * x2.x + v3 * x3.x;
            acc.y += v0 * x0.y + v1 * x1.y + v2 * x2.y + v3 * x3.y;
            acc.z += v0 * x0.z + v1 * x1.z + v2 * x2.z + v3 * x3.z;
            acc.w += v0 * x0.w + v1 * x1.w + v2 * x2.w + v3 * x3.w;
        }
        for (; j < cnt; j++) {
            int   cj = __shfl_sync(0xffffffffu, c, j);
            float vj = __shfl_sync(0xffffffffu, v, j);
            float4 x = ((const float4*)(fb + (size_t)cj * FD))[lane];
            acc.x += vj * x.x; acc.y += vj * x.y;
            acc.z += vj * x.z; acc.w += vj * x.w;
        }
    }
    ((float4*)(g_Lx + (size_t)r * D))[lane] = acc;
}

// ---------------------------------------------------------------------------
// Tensor-core dual-GEMM via mma.sync, full fp16, 3 smem tiles.
// __launch_bounds__(512, 2): cap regs at 64 -> 2 CTAs/SM so fill/sync/epilogue
// of one CTA overlaps the other's MMA stream. Bias moved to epilogue to cut
// early register pressure.
// ---------------------------------------------------------------------------
__global__ void __launch_bounds__(512, 2) k_gemm_mma(const float* __restrict__ blin,
                                                     const float* __restrict__ bint,
                                                     int layer) {
    extern __shared__ char dsm[];
    __shared__ float sPart[128][4];

    char* sS = dsm;
    char* sP = dsm + TILE_B;
    char* sB = dsm + 2 * TILE_B;
    uint32_t uBase = smem_u32(dsm);
    uint32_t uB = uBase + 2 * TILE_B;

    int tid = threadIdx.x;
    int wid = tid >> 5;
    int lane = tid & 31;
    int rbase = blockIdx.x * 128;
    int wm = wid & 3, wn = wid >> 2;
    int m0 = wm * 32, n0 = wn * 32;
    int g = lane >> 2, t = lane & 3;

    float c[2][4][4];
    #pragma unroll
    for (int mt = 0; mt < 2; mt++)
        #pragma unroll
        for (int j = 0; j < 4; j++)
            #pragma unroll
            for (int q = 0; q < 4; q++) c[mt][j][q] = 0.f;

    int aRow = m0 + (lane & 15);
    uint32_t aOff0 = (uint32_t)(aRow * TPITCH_B + (lane >> 4) * 16);
    uint32_t aOff1 = aOff0 + 16 * TPITCH_B;
    int bRow = n0 + ((lane >> 4) << 3) + (lane & 7);
    uint32_t bOff0 = (uint32_t)(bRow * TPITCH_B + ((lane >> 3) & 1) * 16);
    uint32_t bOff1 = bOff0 + 16 * TPITCH_B;

    // ---- Single A fill: both fp16 A tiles ----
    for (int gg = tid; gg < 2048; gg += 512) {
        int m = gg >> 4;
        int kg = (gg & 15) << 3;
        int r = rbase + m;
        uint32_t sv[4], pv[4];
        if (r < NTOT) {
            const float4* lp4 = (const float4*)(g_Lx + (size_t)r * D + kg);
            const float4* fp4 = (const float4*)(g_final + (size_t)r * FD + (size_t)layer * D + kg);
            float4 l0 = lp4[0], l1 = lp4[1];
            float4 f0 = fp4[0], f1 = fp4[1];
            __half2 h;
            h = __floats2half2_rn(l0.x + f0.x, l0.y + f0.y); sv[0] = *(uint32_t*)&h;
            h = __floats2half2_rn(l0.z + f0.z, l0.w + f0.w); sv[1] = *(uint32_t*)&h;
            h = __floats2half2_rn(l1.x + f1.x, l1.y + f1.y); sv[2] = *(uint32_t*)&h;
            h = __floats2half2_rn(l1.z + f1.z, l1.w + f1.w); sv[3] = *(uint32_t*)&h;
            h = __floats2half2_rn(l0.x * f0.x, l0.y * f0.y); pv[0] = *(uint32_t*)&h;
            h = __floats2half2_rn(l0.z * f0.z, l0.w * f0.w); pv[1] = *(uint32_t*)&h;
            h = __floats2half2_rn(l1.x * f1.x, l1.y * f1.y); pv[2] = *(uint32_t*)&h;
            h = __floats2half2_rn(l1.z * f1.z, l1.w * f1.w); pv[3] = *(uint32_t*)&h;
        } else {
            sv[0] = sv[1] = sv[2] = sv[3] = 0u;
            pv[0] = pv[1] = pv[2] = pv[3] = 0u;
        }
        int off = m * TPITCH_B + kg * 2;
        *(uint4*)(sS + off) = make_uint4(sv[0], sv[1], sv[2], sv[3]);
        *(uint4*)(sP + off) = make_uint4(pv[0], pv[1], pv[2], pv[3]);
    }

    #pragma unroll 1
    for (int phase = 0; phase < 2; phase++) {
        if (phase == 1) __syncthreads();  // phase0 B reads done before overwrite
        {
            const uint32_t* src = g_wimg + (size_t)(layer * 2 + phase) * 8192;
            for (int i = tid; i < 2048; i += 512) {
                int n = i >> 4;
                int jj = i & 15;
                *(uint4*)(sB + n * TPITCH_B + jj * 16) = ((const uint4*)(src + n * 64))[jj];
            }
        }
        __syncthreads();

        uint32_t uA = uBase + (phase == 0 ? 0 : TILE_B);

        #pragma unroll
        for (int ks = 0; ks < 8; ks++) {
            uint32_t kb = (uint32_t)(ks * 32);
            uint32_t a[2][4], b[2][4];
            ldsm4(a[0], uA + aOff0 + kb);
            ldsm4(a[1], uA + aOff1 + kb);
            ldsm4(b[0], uB + bOff0 + kb);
            ldsm4(b[1], uB + bOff1 + kb);
            #pragma unroll
            for (int mt = 0; mt < 2; mt++) {
                #pragma unroll
                for (int j = 0; j < 4; j++) {
                    mma16816h(c[mt][j], a[mt],
                              b[j >> 1][(j & 1) * 2], b[j >> 1][(j & 1) * 2 + 1]);
                }
            }
        }
    }

    // ---- Epilogue: bias, leaky, cross-warp row norms, store ----
    #pragma unroll
    for (int j = 0; j < 4; j++) {
        int col0 = n0 + j * 8 + 2 * t;
        float b0 = __ldg(blin + (size_t)layer * D + col0) + __ldg(bint + (size_t)layer * D + col0);
        float b1 = __ldg(blin + (size_t)layer * D + col0 + 1) + __ldg(bint + (size_t)layer * D + col0 + 1);
        #pragma unroll
        for (int mt = 0; mt < 2; mt++) {
            c[mt][j][0] += b0; c[mt][j][1] += b1;
            c[mt][j][2] += b0; c[mt][j][3] += b1;
        }
    }
    #pragma unroll
    for (int mt = 0; mt < 2; mt++)
        #pragma unroll
        for (int j = 0; j < 4; j++)
            #pragma unroll
            for (int q = 0; q < 4; q++) {
                float v = c[mt][j][q];
                c[mt][j][q] = v > 0.f ? v : 0.01f * v;
            }

    float ss[2][2] = {{0.f, 0.f}, {0.f, 0.f}};
    #pragma unroll
    for (int mt = 0; mt < 2; mt++)
        #pragma unroll
        for (int j = 0; j < 4; j++) {
            ss[mt][0] += c[mt][j][0] * c[mt][j][0] + c[mt][j][1] * c[mt][j][1];
            ss[mt][1] += c[mt][j][2] * c[mt][j][2] + c[mt][j][3] * c[mt][j][3];
        }
    #pragma unroll
    for (int o = 1; o <= 2; o <<= 1) {
        #pragma unroll
        for (int mt = 0; mt < 2; mt++) {
            ss[mt][0] += __shfl_xor_sync(0xffffffffu, ss[mt][0], o);
            ss[mt][1] += __shfl_xor_sync(0xffffffffu, ss[mt][1], o);
        }
    }
    if (t == 0) {
        #pragma unroll
        for (int mt = 0; mt < 2; mt++) {
            sPart[m0 + mt * 16 + g][wn] = ss[mt][0];
            sPart[m0 + mt * 16 + g + 8][wn] = ss[mt][1];
        }
    }
    __syncthreads();

    #pragma unroll
    for (int mt = 0; mt < 2; mt++) {
        #pragma unroll
        for (int h = 0; h < 2; h++) {
            int row = m0 + mt * 16 + g + h * 8;
            float tot = sPart[row][0] + sPart[row][1] + sPart[row][2] + sPart[row][3];
            float scale = 1.0f / fmaxf(sqrtf(tot), 1e-12f);
            int rg = rbase + row;
            if (rg < NTOT) {
                float* dst = g_final + (size_t)rg * FD + (size_t)(layer + 1) * D;
                #pragma unroll
                for (int j = 0; j < 4; j++) {
                    int col0 = n0 + j * 8 + 2 * t;
                    *(float2*)(dst + col0) =
                        make_float2(c[mt][j][h * 2] * scale, c[mt][j][h * 2 + 1] * scale);
                }
            }
        }
    }
}

// ---------------------------------------------------------------------------
// Final dot
// ---------------------------------------------------------------------------
__global__ void k_dot(const int* __restrict__ uIdx, const int* __restrict__ iIdx,
                      float* __restrict__ out) {
    int b = blockIdx.x * (blockDim.x >> 5) + (threadIdx.x >> 5);
    if (b >= BATCH) return;
    int lane = threadIdx.x & 31;
    int u = uIdx[b];
    int it = iIdx[b] + NUM_USERS;
    const float4* pu = (const float4*)(g_final + (size_t)u * FD);
    const float4* pi = (const float4*)(g_final + (size_t)it * FD);
    float s = 0.f;
    #pragma unroll
    for (int q = 0; q < 4; q++) {
        float4 a = pu[lane + 32 * q];
        float4 c = pi[lane + 32 * q];
        s += a.x * c.x + a.y * c.y + a.z * c.z + a.w * c.w;
    }
    #pragma unroll
    for (int o = 16; o > 0; o >>= 1)
        s += __shfl_xor_sync(0xffffffffu, s, o);
    if (lane == 0) out[b] = s;
}

// ---------------------------------------------------------------------------
extern "C" void kernel_launch(void* const* d_in, const int* in_sizes, int n_in,
                              void* d_out, int out_size) {
    const int*   userIdx = (const int*)d_in[0];
    const int*   itemIdx = (const int*)d_in[1];
    const int*   rows    = (const int*)d_in[2];
    const int*   cols    = (const int*)d_in[3];
    const float* vals    = (const float*)d_in[4];
    const float* uE      = (const float*)d_in[5];
    const float* iE      = (const float*)d_in[6];
    const float* Wlin    = (const float*)d_in[7];
    const float* blin    = (const float*)d_in[8];
    const float* Wint    = (const float*)d_in[9];
    const float* bint    = (const float*)d_in[10];
    float* out = (float*)d_out;

    const int smem_mma = 3 * TILE_B;  // 104448 B -> 2 CTAs/SM (with 64-reg cap)
    cudaFuncSetAttribute(k_gemm_mma, cudaFuncAttributeMaxDynamicSharedMemorySize, smem_mma);

    const int vec_total = NTOT * (D / 4);
    k_init<<<(vec_total + 255) / 256, 256>>>(uE, iE);   // also zeroes g_cnt
    k_wconv<<<(3 * 2 * 128 * 64 + 255) / 256, 256>>>(Wlin, Wint);

    // CSR build (once per launch)
    k_count<<<(NNZ + 255) / 256, 256>>>(rows);
    k_scan1<<<SCAN_NB, 256>>>();
    k_scan2<<<1, 128>>>();
    k_scan3<<<(NTOT + 255) / 256, 256>>>();
    k_scatter<<<(NNZ + 255) / 256, 256>>>(rows, cols, vals);

    for (int l = 0; l < NLAYERS; l++) {
        k_spmm_csr<<<(NTOT + 7) / 8, 256>>>(l);
        k_gemm_mma<<<(NTOT + 127) / 128, 512, smem_mma>>>(blin, bint, l);
    }

    k_dot<<<(BATCH + 7) / 8, 256>>>(userIdx, itemIdx, out);
}